// round 4
// baseline (speedup 1.0000x reference)
#include <cuda_runtime.h>
#include <cuda_fp16.h>
#include <cstdint>

// Problem dims
#define NL 16
#define DH 128
#define G4 512      // 4*H
#define BB 32
#define TT 512
#define NH 2048     // N*H
#define STRD 136    // padded halves per row (conflict-free LDS)

// x_proj scratch: [n][b][t][4H] fp32 = 512 MB
__device__ float g_xproj[(size_t)NL * BB * TT * G4];

// ---------------- mma.sync m16n8k16 (fp16 in, fp32 acc) ----------------
__device__ __forceinline__ void mma16816(float* d, const uint32_t* a,
                                         uint32_t b0, uint32_t b1) {
    asm volatile("mma.sync.aligned.m16n8k16.row.col.f32.f16.f16.f32 "
                 "{%0,%1,%2,%3}, {%4,%5,%6,%7}, {%8,%9}, {%0,%1,%2,%3};"
                 : "+f"(d[0]), "+f"(d[1]), "+f"(d[2]), "+f"(d[3])
                 : "r"(a[0]), "r"(a[1]), "r"(a[2]), "r"(a[3]), "r"(b0), "r"(b1));
}

// exact-path activations (EX2+RCP, ~1e-6 rel err)
__device__ __forceinline__ float sigm(float x) {
    return __fdividef(1.0f, 1.0f + __expf(-x));
}
__device__ __forceinline__ float tanh_f(float x) {
    float ax = fabsf(x);
    float e = __expf(-2.0f * ax);
    float r = __fdividef(1.0f - e, 1.0f + e);
    return copysignf(r, x);
}

// =================================================================
// Phase 1: x_proj[n][b][t][r] = W_ih[n] . x[b,t,nI:] + b_ih + b_hh
// grid (TT/128, BB, NL) = 2048 CTAs, 256 threads
// =================================================================
#define P1_TB 128
#define P1_SMEM ((G4 * STRD + P1_TB * STRD) * 2)

__global__ void __launch_bounds__(256, 1) wlstm_xproj(
    const float* __restrict__ x, const float* __restrict__ Wih,
    const float* __restrict__ bih, const float* __restrict__ bhh)
{
    extern __shared__ char p1smem[];
    __half* ws = (__half*)p1smem;                       // [512][STRD]
    __half* xs = (__half*)(p1smem + G4 * STRD * 2);     // [P1_TB][STRD]

    const int tid = threadIdx.x, wid = tid >> 5, lane = tid & 31;
    const int n = blockIdx.z, b = blockIdx.y, t0 = blockIdx.x * P1_TB;
    const int g0 = lane >> 2, cq = lane & 3;

    // W_ih[n] fp32 -> fp16 SMEM
    const float* W = Wih + (size_t)n * G4 * DH;
    for (int idx = tid; idx < G4 * DH; idx += 256) {
        int r = idx >> 7, k = idx & 127;
        ws[r * STRD + k] = __float2half(W[idx]);
    }
    // x tile [t_local][i]
    const float* xp = x + ((size_t)b * TT + t0) * NH + n * DH;
    for (int idx = tid; idx < P1_TB * DH; idx += 256) {
        int tl = idx >> 7, i = idx & 127;
        xs[tl * STRD + i] = __float2half(xp[(size_t)tl * NH + i]);
    }
    __syncthreads();

    // A-fragments in registers: warp w owns m-tiles {w, w+8, w+16, w+24}
    uint32_t a[4][8][4];
    const uint32_t* ws32 = (const uint32_t*)ws;
#pragma unroll
    for (int mi = 0; mi < 4; mi++) {
        int r0 = (wid + 8 * mi) * 16 + g0;
#pragma unroll
        for (int kc = 0; kc < 8; kc++) {
            int kw = kc * 8 + cq;   // word offset of k0=kc*16+cq*2
            a[mi][kc][0] = ws32[r0 * (STRD / 2) + kw];
            a[mi][kc][1] = ws32[(r0 + 8) * (STRD / 2) + kw];
            a[mi][kc][2] = ws32[r0 * (STRD / 2) + kw + 4];
            a[mi][kc][3] = ws32[(r0 + 8) * (STRD / 2) + kw + 4];
        }
    }
    float bias[4][2];
#pragma unroll
    for (int mi = 0; mi < 4; mi++) {
        int r0 = (wid + 8 * mi) * 16 + g0;
        bias[mi][0] = bih[n * G4 + r0] + bhh[n * G4 + r0];
        bias[mi][1] = bih[n * G4 + r0 + 8] + bhh[n * G4 + r0 + 8];
    }

    const uint32_t* xs32 = (const uint32_t*)xs;
    float* ob = g_xproj + ((size_t)(n * BB + b) * TT + t0) * G4;

    for (int nt = 0; nt < P1_TB / 8; nt++) {
        float d[4][4];
#pragma unroll
        for (int mi = 0; mi < 4; mi++)
#pragma unroll
            for (int q = 0; q < 4; q++) d[mi][q] = 0.0f;

        int col = nt * 8 + g0;   // B-frag column (t_local)
#pragma unroll
        for (int kc = 0; kc < 8; kc++) {
            uint32_t b0 = xs32[col * (STRD / 2) + kc * 8 + cq];
            uint32_t b1 = xs32[col * (STRD / 2) + kc * 8 + cq + 4];
#pragma unroll
            for (int mi = 0; mi < 4; mi++) mma16816(d[mi], a[mi][kc], b0, b1);
        }
        // store: D cols = t_local {2cq, 2cq+1}, rows {r0, r0+8}
        int tc = nt * 8 + 2 * cq;
#pragma unroll
        for (int mi = 0; mi < 4; mi++) {
            int r0 = (wid + 8 * mi) * 16 + g0;
            ob[(size_t)tc * G4 + r0]           = d[mi][0] + bias[mi][0];
            ob[(size_t)(tc + 1) * G4 + r0]     = d[mi][1] + bias[mi][0];
            ob[(size_t)tc * G4 + r0 + 8]       = d[mi][2] + bias[mi][1];
            ob[(size_t)(tc + 1) * G4 + r0 + 8] = d[mi][3] + bias[mi][1];
        }
    }
}

// =================================================================
// Phase 2: persistent recurrence. grid 128 = n(16) x bc(8, 4 batches)
// 256 threads (8 warps). W_hh entirely in registers as A-fragments.
// =================================================================
__global__ void __launch_bounds__(256, 1) wlstm_rec(
    const float* __restrict__ Whh, float* __restrict__ out)
{
    __shared__ __half hs[8 * STRD];   // h tile: [8 cols (batch, 4 pad)][128 j]

    const int tid = threadIdx.x, wid = tid >> 5, lane = tid & 31;
    const int n = blockIdx.x >> 3, bc = blockIdx.x & 7;
    const int g0 = lane >> 2, cq = lane & 3;
    const bool act = (cq < 2);        // D cols 2cq,2cq+1 real iff < 4

    for (int i = tid; i < 8 * STRD; i += 256) hs[i] = __float2half(0.0f);

    // W_hh[n] -> A-fragments (128 regs/thread)
    uint32_t a[4][8][4];
    const float* W = Whh + (size_t)n * G4 * DH;
#pragma unroll
    for (int mi = 0; mi < 4; mi++) {
        int r0 = (wid + 8 * mi) * 16 + g0;
#pragma unroll
        for (int kc = 0; kc < 8; kc++) {
            int k0 = kc * 16 + cq * 2;
            float2 w00 = *(const float2*)(W + (size_t)r0 * DH + k0);
            float2 w10 = *(const float2*)(W + (size_t)(r0 + 8) * DH + k0);
            float2 w01 = *(const float2*)(W + (size_t)r0 * DH + k0 + 8);
            float2 w11 = *(const float2*)(W + (size_t)(r0 + 8) * DH + k0 + 8);
            __half2 h00 = __floats2half2_rn(w00.x, w00.y);
            __half2 h10 = __floats2half2_rn(w10.x, w10.y);
            __half2 h01 = __floats2half2_rn(w01.x, w01.y);
            __half2 h11 = __floats2half2_rn(w11.x, w11.y);
            a[mi][kc][0] = *(uint32_t*)&h00;
            a[mi][kc][1] = *(uint32_t*)&h10;
            a[mi][kc][2] = *(uint32_t*)&h01;
            a[mi][kc][3] = *(uint32_t*)&h11;
        }
    }

    // per-thread state: (rr in {0,1} -> j = 16w+g0+8rr ; bb in {0,1} -> b = bc*4+2cq+bb)
    const int jj[2] = { 16 * wid + g0, 16 * wid + g0 + 8 };
    const int bg[2] = { bc * 4 + 2 * cq, bc * 4 + 2 * cq + 1 };

    const float* xbase[2];
    float* obase[2];
    float cst[4], hst[4];
#pragma unroll
    for (int s = 0; s < 4; s++) { cst[s] = 0.0f; hst[s] = 0.0f; }
    if (act) {
#pragma unroll
        for (int bb = 0; bb < 2; bb++) {
            xbase[bb] = g_xproj + (size_t)(n * BB + bg[bb]) * TT * G4;
            obase[bb] = out + (size_t)bg[bb] * TT * NH + n * DH;
        }
    }

    float xpa[16], xpb[16];   // x_proj double buffer: [mi*4 + rr*2 + bb]
    if (act) {
#pragma unroll
        for (int mi = 0; mi < 4; mi++)
#pragma unroll
            for (int rr = 0; rr < 2; rr++)
#pragma unroll
                for (int bb = 0; bb < 2; bb++)
                    xpa[mi * 4 + rr * 2 + bb] =
                        __ldg(xbase[bb] + mi * 128 + jj[rr]);
    }

    const uint32_t* hs32 = (const uint32_t*)hs;

    auto step = [&](int t, float (&xpc)[16], float (&xpn)[16]) {
        __syncthreads();   // prev-step hs writes visible
        // prefetch x_proj(t+1)
        if (act && t + 1 < TT) {
#pragma unroll
            for (int mi = 0; mi < 4; mi++)
#pragma unroll
                for (int rr = 0; rr < 2; rr++)
#pragma unroll
                    for (int bb = 0; bb < 2; bb++)
                        xpn[mi * 4 + rr * 2 + bb] =
                            __ldg(xbase[bb] + (size_t)(t + 1) * G4 + mi * 128 + jj[rr]);
        }
        // z = W_hh . h
        float d[4][4];
#pragma unroll
        for (int mi = 0; mi < 4; mi++)
#pragma unroll
            for (int q = 0; q < 4; q++) d[mi][q] = 0.0f;
#pragma unroll
        for (int kc = 0; kc < 8; kc++) {
            uint32_t b0 = hs32[g0 * (STRD / 2) + kc * 8 + cq];
            uint32_t b1 = hs32[g0 * (STRD / 2) + kc * 8 + cq + 4];
#pragma unroll
            for (int mi = 0; mi < 4; mi++) mma16816(d[mi], a[mi][kc], b0, b1);
        }
        __syncthreads();   // all warps done reading hs before rewrite
        if (act) {
#pragma unroll
            for (int rr = 0; rr < 2; rr++)
#pragma unroll
                for (int bb = 0; bb < 2; bb++) {
                    int s = rr * 2 + bb;
                    int q = rr * 2 + bb;   // d index: d0,d1 row g0; d2,d3 row g0+8
                    float zi = d[0][q] + xpc[0 + s];
                    float zf = d[1][q] + xpc[4 + s];
                    float zg = d[2][q] + xpc[8 + s];
                    float zo = d[3][q] + xpc[12 + s];
                    float ig = sigm(zi);
                    float fg = sigm(zf);
                    float gg = tanh_f(zg);
                    float og = sigm(zo);
                    float cv = fg * cst[s] + ig * gg;
                    cst[s] = cv;
                    float hv = og * tanh_f(cv);
                    hst[s] = hv;
                    obase[bb][(size_t)t * NH + jj[rr]] = hv;
                    hs[(2 * cq + bb) * STRD + jj[rr]] = __float2half(hv);
                }
        }
    };

    for (int t = 0; t < TT; t += 2) {
        step(t, xpa, xpb);
        step(t + 1, xpb, xpa);
    }

    // h_n, c_n: out layout = [output | h_n | c_n]
    if (act) {
        float* hn = out + (size_t)BB * TT * NH;
        float* cn = hn + (size_t)BB * NH;
#pragma unroll
        for (int rr = 0; rr < 2; rr++)
#pragma unroll
            for (int bb = 0; bb < 2; bb++) {
                int s = rr * 2 + bb;
                hn[(size_t)bg[bb] * NH + n * DH + jj[rr]] = hst[s];
                cn[(size_t)bg[bb] * NH + n * DH + jj[rr]] = cst[s];
            }
    }
}

extern "C" void kernel_launch(void* const* d_in, const int* in_sizes, int n_in,
                              void* d_out, int out_size) {
    const float* x   = (const float*)d_in[0];
    const float* Wih = (const float*)d_in[1];
    const float* Whh = (const float*)d_in[2];
    const float* bih = (const float*)d_in[3];
    const float* bhh = (const float*)d_in[4];
    float* out = (float*)d_out;

    cudaFuncSetAttribute(wlstm_xproj,
                         cudaFuncAttributeMaxDynamicSharedMemorySize, P1_SMEM);

    dim3 g1(TT / P1_TB, BB, NL);
    wlstm_xproj<<<g1, 256, P1_SMEM>>>(x, Wih, bih, bhh);
    wlstm_rec<<<NL * 8, 256>>>(Whh, out);
}

// round 5
// speedup vs baseline: 1.8661x; 1.8661x over previous
#include <cuda_runtime.h>
#include <cuda_fp16.h>
#include <cstdint>

// Problem dims
#define NL 16
#define DH 128
#define G4 512      // 4*H
#define BB 32
#define TT 512
#define NH 2048     // N*H
#define STRD 136    // padded halves per row (conflict-free LDS)

// x_proj scratch: [n][t][b][4H] fp16 = 256 MB (bias folded in at rec prefetch)
__device__ __half g_xp16[(size_t)NL * TT * BB * G4];

// ---------------- mma.sync m16n8k16 (fp16 in, fp32 acc) ----------------
__device__ __forceinline__ void mma16816(float* d, const uint32_t* a,
                                         uint32_t b0, uint32_t b1) {
    asm volatile("mma.sync.aligned.m16n8k16.row.col.f32.f16.f16.f32 "
                 "{%0,%1,%2,%3}, {%4,%5,%6,%7}, {%8,%9}, {%0,%1,%2,%3};"
                 : "+f"(d[0]), "+f"(d[1]), "+f"(d[2]), "+f"(d[3])
                 : "r"(a[0]), "r"(a[1]), "r"(a[2]), "r"(a[3]), "r"(b0), "r"(b1));
}

// sigmoid via HW tanh: sigma(x) = 0.5*tanh(x/2) + 0.5  (1 MUFU)
__device__ __forceinline__ float sigm_apx(float x) {
    float t;
    asm("tanh.approx.f32 %0, %1;" : "=f"(t) : "f"(0.5f * x));
    return fmaf(0.5f, t, 0.5f);
}
// exact-path tanh for the cell path (EX2+RCP, ~1e-6 rel err)
__device__ __forceinline__ float tanh_f(float x) {
    float ax = fabsf(x);
    float e = __expf(-2.0f * ax);
    float r = __fdividef(1.0f - e, 1.0f + e);
    return copysignf(r, x);
}

// =================================================================
// Phase 1: x_proj16[n][t][b][r] = W_ih[n] . x[b,t,nI:]   (no bias)
// grid (4 t-tiles, 8 b-groups, 16 n) = 512 CTAs, 512 threads
// Each CTA: load W once, loop 4 batches.
// =================================================================
#define P1_TB 128
#define P1_SMEM ((G4 * STRD + P1_TB * STRD) * 2)

__global__ void __launch_bounds__(512, 1) wlstm_xproj(
    const float* __restrict__ x, const float* __restrict__ Wih)
{
    extern __shared__ char p1smem[];
    __half* ws = (__half*)p1smem;                       // [512][STRD]
    __half* xs = (__half*)(p1smem + G4 * STRD * 2);     // [128][STRD]

    const int tid = threadIdx.x, wid = tid >> 5, lane = tid & 31;
    const int g0 = lane >> 2, cq = lane & 3;
    const int n = blockIdx.z, bg = blockIdx.y, t0 = blockIdx.x * P1_TB;

    // ---- W_ih[n] fp32 -> fp16 SMEM (float4 loads, MLP-deep)
    const float4* W4 = (const float4*)(Wih + (size_t)n * G4 * DH);
#pragma unroll 4
    for (int i = tid; i < G4 * DH / 4; i += 512) {
        float4 w = W4[i];
        int r = i >> 5, k = (i & 31) * 4;
        __half2 h01 = __floats2half2_rn(w.x, w.y);
        __half2 h23 = __floats2half2_rn(w.z, w.w);
        uint2 v = { *(uint32_t*)&h01, *(uint32_t*)&h23 };
        *(uint2*)(ws + r * STRD + k) = v;
    }
    // ---- x(b0) tile [128 t][128 i]
    {
        int b = bg * 4;
#pragma unroll 4
        for (int i = tid; i < P1_TB * DH / 4; i += 512) {
            int tl = i >> 5, c4 = (i & 31) * 4;
            float4 w = *(const float4*)(x + ((size_t)b * TT + t0 + tl) * NH + n * DH + c4);
            __half2 h01 = __floats2half2_rn(w.x, w.y);
            __half2 h23 = __floats2half2_rn(w.z, w.w);
            uint2 v = { *(uint32_t*)&h01, *(uint32_t*)&h23 };
            *(uint2*)(xs + tl * STRD + c4) = v;
        }
    }
    __syncthreads();

    // ---- A-fragments: warp wid owns m-tiles {2*wid, 2*wid+1}
    uint32_t a[2][8][4];
    const uint32_t* ws32 = (const uint32_t*)ws;
#pragma unroll
    for (int ti = 0; ti < 2; ti++) {
        int r0 = (2 * wid + ti) * 16 + g0;
#pragma unroll
        for (int kc = 0; kc < 8; kc++) {
            int kw = kc * 8 + cq;
            a[ti][kc][0] = ws32[r0 * (STRD / 2) + kw];
            a[ti][kc][1] = ws32[(r0 + 8) * (STRD / 2) + kw];
            a[ti][kc][2] = ws32[r0 * (STRD / 2) + kw + 4];
            a[ti][kc][3] = ws32[(r0 + 8) * (STRD / 2) + kw + 4];
        }
    }

    const uint32_t* xs32 = (const uint32_t*)xs;
    for (int bl = 0; bl < 4; bl++) {
        int b = bg * 4 + bl;
        __half* ob = g_xp16 + ((size_t)(n * TT + t0) * BB + b) * G4;

        for (int nt = 0; nt < P1_TB / 8; nt++) {
            float d[2][4];
#pragma unroll
            for (int ti = 0; ti < 2; ti++)
#pragma unroll
                for (int q = 0; q < 4; q++) d[ti][q] = 0.0f;

            int col = nt * 8 + g0;
#pragma unroll
            for (int kc = 0; kc < 8; kc++) {
                uint32_t b0 = xs32[col * (STRD / 2) + kc * 8 + cq];
                uint32_t b1 = xs32[col * (STRD / 2) + kc * 8 + cq + 4];
#pragma unroll
                for (int ti = 0; ti < 2; ti++) mma16816(d[ti], a[ti][kc], b0, b1);
            }
            // D cols = t {2cq, 2cq+1}, rows {r0, r0+8}
            int tc = nt * 8 + 2 * cq;
#pragma unroll
            for (int ti = 0; ti < 2; ti++) {
                int r0 = (2 * wid + ti) * 16 + g0;
                ob[(size_t)tc * (BB * G4) + r0]           = __float2half(d[ti][0]);
                ob[(size_t)(tc + 1) * (BB * G4) + r0]     = __float2half(d[ti][1]);
                ob[(size_t)tc * (BB * G4) + r0 + 8]       = __float2half(d[ti][2]);
                ob[(size_t)(tc + 1) * (BB * G4) + r0 + 8] = __float2half(d[ti][3]);
            }
        }
        __syncthreads();   // all B-frag reads done before xs overwrite
        if (bl < 3) {
            int bn = bg * 4 + bl + 1;
#pragma unroll 4
            for (int i = tid; i < P1_TB * DH / 4; i += 512) {
                int tl = i >> 5, c4 = (i & 31) * 4;
                float4 w = *(const float4*)(x + ((size_t)bn * TT + t0 + tl) * NH + n * DH + c4);
                __half2 h01 = __floats2half2_rn(w.x, w.y);
                __half2 h23 = __floats2half2_rn(w.z, w.w);
                uint2 v = { *(uint32_t*)&h01, *(uint32_t*)&h23 };
                *(uint2*)(xs + tl * STRD + c4) = v;
            }
            __syncthreads();
        }
    }
}

// =================================================================
// Phase 2: persistent recurrence. grid 128 = (n, bc of 4 batches),
// 512 threads (16 warps). W_hh in registers; z exchanged via SMEM;
// each thread runs exactly ONE (j, b) LSTM state.
// =================================================================
#define ZSTR 520   // fp32 words per batch column in zs (pad for banks)

__global__ void __launch_bounds__(512, 1) wlstm_rec(
    const float* __restrict__ Whh, const float* __restrict__ bih,
    const float* __restrict__ bhh, float* __restrict__ out)
{
    __shared__ __half hs[2][8][STRD];   // double-buffered h tile [buf][bcol][j]
    __shared__ float  zs[4 * ZSTR];     // z exchange: [batch][512 gate rows]

    const int tid = threadIdx.x, wid = tid >> 5, lane = tid & 31;
    const int g0 = lane >> 2, cq = lane & 3;
    const int n = blockIdx.x >> 3, bc = blockIdx.x & 7;

    // zero both h buffers (incl. pad cols 4..7 which stay zero forever)
    for (int i = tid; i < 2 * 8 * STRD; i += 512) ((__half*)hs)[i] = __float2half(0.0f);

    // ---- W_hh[n] -> A-fragments (warp wid owns m-tiles {wid, wid+16})
    uint32_t a[2][8][4];
    const float* W = Whh + (size_t)n * G4 * DH;
#pragma unroll
    for (int ti = 0; ti < 2; ti++) {
        int r0 = (wid + 16 * ti) * 16 + g0;
#pragma unroll
        for (int kc = 0; kc < 8; kc++) {
            int k0 = kc * 16 + cq * 2;
            float2 w00 = *(const float2*)(W + (size_t)r0 * DH + k0);
            float2 w10 = *(const float2*)(W + (size_t)(r0 + 8) * DH + k0);
            float2 w01 = *(const float2*)(W + (size_t)r0 * DH + k0 + 8);
            float2 w11 = *(const float2*)(W + (size_t)(r0 + 8) * DH + k0 + 8);
            __half2 h00 = __floats2half2_rn(w00.x, w00.y);
            __half2 h10 = __floats2half2_rn(w10.x, w10.y);
            __half2 h01 = __floats2half2_rn(w01.x, w01.y);
            __half2 h11 = __floats2half2_rn(w11.x, w11.y);
            a[ti][kc][0] = *(uint32_t*)&h00;
            a[ti][kc][1] = *(uint32_t*)&h10;
            a[ti][kc][2] = *(uint32_t*)&h01;
            a[ti][kc][3] = *(uint32_t*)&h11;
        }
    }

    // ---- per-thread LSTM state: j = tid&127, local batch bl = tid>>7
    const int j  = tid & 127;
    const int bl = tid >> 7;
    const int b  = bc * 4 + bl;

    float bias[4];
#pragma unroll
    for (int g = 0; g < 4; g++)
        bias[g] = bih[n * G4 + g * 128 + j] + bhh[n * G4 + g * 128 + j];

    const __half* xq = g_xp16 + ((size_t)(n * TT) * BB + b) * G4 + j;  // +t*BB*G4
    float* ob = out + (size_t)b * TT * NH + n * DH + j;

    float xpa[4], xpb[4];
#pragma unroll
    for (int g = 0; g < 4; g++)
        xpa[g] = __half2float(xq[g * 128]) + bias[g];

    float cst = 0.0f, hst = 0.0f;
    __syncthreads();

    auto step = [&](int t, float (&xpc)[4], float (&xpn)[4]) {
        // prefetch x_proj(t+1) early (hidden behind mma)
        if (t + 1 < TT) {
            const __half* xn = xq + (size_t)(t + 1) * (BB * G4);
#pragma unroll
            for (int g = 0; g < 4; g++)
                xpn[g] = __half2float(xn[g * 128]) + bias[g];
        }
        // ---- z = W_hh . h_{t-1}
        const uint32_t* hb = (const uint32_t*)hs[t & 1];
        float d[2][4];
#pragma unroll
        for (int ti = 0; ti < 2; ti++)
#pragma unroll
            for (int q = 0; q < 4; q++) d[ti][q] = 0.0f;
#pragma unroll
        for (int kc = 0; kc < 8; kc++) {
            uint32_t b0 = hb[g0 * (STRD / 2) + kc * 8 + cq];
            uint32_t b1 = hb[g0 * (STRD / 2) + kc * 8 + cq + 4];
#pragma unroll
            for (int ti = 0; ti < 2; ti++) mma16816(d[ti], a[ti][kc], b0, b1);
        }
        // stash z for real batches (D cols 0..3 <-> cq 0,1)
        if (cq < 2) {
#pragma unroll
            for (int ti = 0; ti < 2; ti++) {
                int r0 = (wid + 16 * ti) * 16 + g0;
                zs[(2 * cq) * ZSTR + r0]         = d[ti][0];
                zs[(2 * cq + 1) * ZSTR + r0]     = d[ti][1];
                zs[(2 * cq) * ZSTR + r0 + 8]     = d[ti][2];
                zs[(2 * cq + 1) * ZSTR + r0 + 8] = d[ti][3];
            }
        }
        __syncthreads();   // z visible to all

        // ---- epilogue: one state per thread
        float zi = zs[bl * ZSTR + j]       + xpc[0];
        float zf = zs[bl * ZSTR + 128 + j] + xpc[1];
        float zg = zs[bl * ZSTR + 256 + j] + xpc[2];
        float zo = zs[bl * ZSTR + 384 + j] + xpc[3];
        float ig = sigm_apx(zi);
        float fg = sigm_apx(zf);
        float gg = tanh_f(zg);
        float og = sigm_apx(zo);
        cst = fg * cst + ig * gg;
        hst = og * tanh_f(cst);

        ob[(size_t)t * NH] = hst;
        hs[(t + 1) & 1][bl][j] = __float2half(hst);
        __syncthreads();   // hs(t) visible + zs reads done before next mma
    };

    for (int t = 0; t < TT; t += 2) {
        step(t, xpa, xpb);
        step(t + 1, xpb, xpa);
    }

    // h_n, c_n: out = [output | h_n | c_n]
    float* hn = out + (size_t)BB * TT * NH + (size_t)b * NH + n * DH + j;
    hn[0] = hst;
    hn[(size_t)BB * NH] = cst;
}

extern "C" void kernel_launch(void* const* d_in, const int* in_sizes, int n_in,
                              void* d_out, int out_size) {
    const float* x   = (const float*)d_in[0];
    const float* Wih = (const float*)d_in[1];
    const float* Whh = (const float*)d_in[2];
    const float* bih = (const float*)d_in[3];
    const float* bhh = (const float*)d_in[4];
    float* out = (float*)d_out;

    cudaFuncSetAttribute(wlstm_xproj,
                         cudaFuncAttributeMaxDynamicSharedMemorySize, P1_SMEM);

    dim3 g1(TT / P1_TB, BB / 4, NL);   // (4, 8, 16) = 512 CTAs
    wlstm_xproj<<<g1, 512, P1_SMEM>>>(x, Wih);
    wlstm_rec<<<NL * 8, 512>>>(Whh, bih, bhh, out);
}